// round 14
// baseline (speedup 1.0000x reference)
#include <cuda_runtime.h>
#include <cuda_fp16.h>
#include <cstdint>

// Problem constants
#define Bb 2
#define Ss 2048
#define Dd 2048
#define Hh 16
#define HDd 128
#define MROWS (Bb*Ss)              // 4096
#define ATTN_SCALE 0.08838834764831845f  // 1/sqrt(128)

// Scratch (static device globals: allocation-free rule)
__device__ __half g_Xh[(size_t)MROWS*Dd];
__device__ __half g_Wh[4][(size_t)Dd*Dd];
__device__ __half g_Qh[(size_t)MROWS*Dd];
__device__ __half g_Kh[(size_t)MROWS*Dd];
__device__ __half g_Vh[(size_t)MROWS*Dd];
__device__ __half g_Ah[(size_t)MROWS*Dd];

// ------------------------------------------------------------------
// helpers
// ------------------------------------------------------------------
__device__ __forceinline__ uint32_t pk2(float a, float b){
    __half2 h = __floats2half2_rn(a, b);
    return *reinterpret_cast<uint32_t*>(&h);
}
__device__ __forceinline__ uint32_t smem_u32(const void* p){
    uint32_t a;
    asm("{ .reg .u64 t; cvta.to.shared.u64 t, %1; cvt.u32.u64 %0, t; }"
        : "=r"(a) : "l"(p));
    return a;
}
__device__ __forceinline__ void mma_f16(float c[4], const uint32_t a[4],
                                        uint32_t b0, uint32_t b1){
    asm volatile("mma.sync.aligned.m16n8k16.row.col.f32.f16.f16.f32 "
        "{%0,%1,%2,%3}, {%4,%5,%6,%7}, {%8,%9}, {%0,%1,%2,%3};\n"
        : "+f"(c[0]), "+f"(c[1]), "+f"(c[2]), "+f"(c[3])
        : "r"(a[0]), "r"(a[1]), "r"(a[2]), "r"(a[3]), "r"(b0), "r"(b1));
}
__device__ __forceinline__ void ldm_x4(uint32_t &r0, uint32_t &r1,
                                       uint32_t &r2, uint32_t &r3, uint32_t addr){
    asm volatile("ldmatrix.sync.aligned.m8n8.x4.shared.b16 {%0,%1,%2,%3}, [%4];"
        : "=r"(r0), "=r"(r1), "=r"(r2), "=r"(r3) : "r"(addr));
}
__device__ __forceinline__ void ldm_x4_t(uint32_t &r0, uint32_t &r1,
                                         uint32_t &r2, uint32_t &r3, uint32_t addr){
    asm volatile("ldmatrix.sync.aligned.m8n8.x4.trans.shared.b16 {%0,%1,%2,%3}, [%4];"
        : "=r"(r0), "=r"(r1), "=r"(r2), "=r"(r3) : "r"(addr));
}

#define CP_ASYNC16(sa, ga) \
    asm volatile("cp.async.cg.shared.global [%0], [%1], 16;" :: "r"(sa), "l"(ga))
#define CP_COMMIT() asm volatile("cp.async.commit_group;" ::: "memory")
#define CP_WAIT(n)  asm volatile("cp.async.wait_group %0;" :: "n"(n) : "memory")

// ------------------------------------------------------------------
// pack fp32 -> fp16
// ------------------------------------------------------------------
__global__ void pack_half(const float4* __restrict__ in, uint32_t* __restrict__ out,
                          int n4){
    int i = blockIdx.x * blockDim.x + threadIdx.x;
    if (i < n4) {
        float4 v = in[i];
        out[2*i]   = pk2(v.x, v.y);
        out[2*i+1] = pk2(v.z, v.w);
    }
}
__global__ void pack_half2(const float4* __restrict__ in0, uint32_t* __restrict__ out0,
                           const float4* __restrict__ in1, uint32_t* __restrict__ out1,
                           int n4){
    int i = blockIdx.x * blockDim.x + threadIdx.x;
    if (i >= n4) return;
    const float4* in = blockIdx.y ? in1 : in0;
    uint32_t* out = blockIdx.y ? out1 : out0;
    float4 v = in[i];
    out[2*i]   = pk2(v.x, v.y);
    out[2*i+1] = pk2(v.z, v.w);
}

// ------------------------------------------------------------------
// GEMM core: C[M,N] = A[M,K] * W[N,K]^T   (fp16 m16n8k16, fp32 accum)
// 128x256 CTA, 8 warps (2x4) of 64x64, BK=32 halves, 4-stage cp.async,
// 1 CTA/SM, ~190 regs. Per k16-step: 8 ldmatrix.x4 -> 32 independent mmas.
// ------------------------------------------------------------------
#define GM 4096
#define GN 2048
#define GK 2048
#define BKH 32
#define SSTR 20
#define A_WORDS (128*SSTR)              // 2560 words
#define B_WORDS (256*SSTR)              // 5120 words
#define STG_WORDS (A_WORDS + B_WORDS)   // 7680 words = 30720 B
#define G_STAGES 4
#define G_SMEM (G_STAGES*STG_WORDS*4)   // 122880 B
#define G_NK (GK/BKH)                   // 64

__device__ __forceinline__ void gemm_core(const __half* __restrict__ A,
                                          const __half* __restrict__ W,
                                          void* __restrict__ Cv, int outh,
                                          uint32_t smem_base)
{
    const int tid  = threadIdx.x;
    const int lane = tid & 31, warp = tid >> 5;
    const int wm = warp >> 2, wn = warp & 3;      // 2 x 4 warp grid (64x64 tiles)
    const int g = lane >> 2, t = lane & 3;
    const int bM = blockIdx.y * 128, bN = blockIdx.x * 256;

    // fill: 16B chunks. A tile 512 chunks (2/thread), B tile 1024 (4/thread).
    const int frow = tid >> 2, fc = tid & 3;
    const __half* Ag = A + (size_t)(bM + frow) * GK + fc * 8;
    const __half* Wg = W + (size_t)(bN + frow) * GK + fc * 8;
    const uint32_t fillA = smem_base + (uint32_t)(frow * SSTR + fc * 4) * 4u;
    const uint32_t fillB = smem_base + (uint32_t)(A_WORDS + frow * SSTR + fc * 4) * 4u;

    // ldmatrix lane address components
    const int a_row = wm*64 + (lane & 15);                 // + mt*16
    const int a_col = (lane >> 4) << 2;                    // + ks*8
    const int b_row = wn*64 + (lane & 7) + ((lane >> 4) << 3);   // + p*16
    const int b_col = ((lane >> 3) & 1) << 2;              // + ks*8
    const uint32_t aoff = (uint32_t)(a_row * SSTR + a_col) * 4u;
    const uint32_t boff = (uint32_t)(A_WORDS + b_row * SSTR + b_col) * 4u;

    float acc[4][8][4];
    #pragma unroll
    for (int mt = 0; mt < 4; mt++)
        #pragma unroll
        for (int nt = 0; nt < 8; nt++)
            #pragma unroll
            for (int e = 0; e < 4; e++) acc[mt][nt][e] = 0.f;

    // prologue: fill stages 0..2
    #pragma unroll
    for (int s = 0; s < G_STAGES - 1; s++) {
        uint32_t sa = fillA + s * (STG_WORDS * 4);
        uint32_t sw = fillB + s * (STG_WORDS * 4);
        const __half* ap = Ag + s * BKH;
        const __half* wp = Wg + s * BKH;
        CP_ASYNC16(sa, ap);
        CP_ASYNC16(sa + 64*SSTR*4, ap + (size_t)64 * GK);
        #pragma unroll
        for (int i = 0; i < 4; i++)
            CP_ASYNC16(sw + i*64*SSTR*4, wp + (size_t)(64*i) * GK);
        CP_COMMIT();
    }

    for (int kt = 0; kt < G_NK; kt++) {
        CP_WAIT(2);
        __syncthreads();

        {   // prefetch tile kt+3 into slot (kt+3)%4
            const int pf = kt + G_STAGES - 1;
            if (pf < G_NK) {
                const int sp = pf & (G_STAGES - 1);
                uint32_t sa = fillA + sp * (STG_WORDS * 4);
                uint32_t sw = fillB + sp * (STG_WORDS * 4);
                const __half* ap = Ag + pf * BKH;
                const __half* wp = Wg + pf * BKH;
                CP_ASYNC16(sa, ap);
                CP_ASYNC16(sa + 64*SSTR*4, ap + (size_t)64 * GK);
                #pragma unroll
                for (int i = 0; i < 4; i++)
                    CP_ASYNC16(sw + i*64*SSTR*4, wp + (size_t)(64*i) * GK);
            }
            CP_COMMIT();
        }

        const uint32_t sbase = smem_base + (kt & (G_STAGES - 1)) * (STG_WORDS * 4);
        #pragma unroll
        for (int ks = 0; ks < 2; ks++) {        // k halves 0-15, 16-31
            const uint32_t kso = (uint32_t)(ks * 8) * 4u;
            uint32_t af[4][4], bf[8][2];
            #pragma unroll
            for (int mt = 0; mt < 4; mt++)
                ldm_x4(af[mt][0], af[mt][1], af[mt][2], af[mt][3],
                       sbase + aoff + kso + (uint32_t)(mt*16*SSTR)*4u);
            #pragma unroll
            for (int p = 0; p < 4; p++)
                ldm_x4(bf[2*p][0], bf[2*p][1], bf[2*p+1][0], bf[2*p+1][1],
                       sbase + boff + kso + (uint32_t)(p*16*SSTR)*4u);
            #pragma unroll
            for (int mt = 0; mt < 4; mt++)
                #pragma unroll
                for (int nt = 0; nt < 8; nt++)
                    mma_f16(acc[mt][nt], af[mt], bf[nt][0], bf[nt][1]);
        }
        __syncthreads();
    }

    // epilogue
    if (outh) {
        uint32_t* Cw = (uint32_t*)Cv;
        #pragma unroll
        for (int mt = 0; mt < 4; mt++) {
            int r = bM + wm*64 + mt*16 + g;
            #pragma unroll
            for (int nt = 0; nt < 8; nt++) {
                int c = bN + wn*64 + nt*8 + t*2;
                Cw[(size_t)r * (GN/2)       + (c >> 1)] = pk2(acc[mt][nt][0], acc[mt][nt][1]);
                Cw[(size_t)(r + 8) * (GN/2) + (c >> 1)] = pk2(acc[mt][nt][2], acc[mt][nt][3]);
            }
        }
    } else {
        float* C = (float*)Cv;
        #pragma unroll
        for (int mt = 0; mt < 4; mt++) {
            int r = bM + wm*64 + mt*16 + g;
            #pragma unroll
            for (int nt = 0; nt < 8; nt++) {
                int c = bN + wn*64 + nt*8 + t*2;
                *(float2*)&C[(size_t)r * GN + c]       = make_float2(acc[mt][nt][0], acc[mt][nt][1]);
                *(float2*)&C[(size_t)(r + 8) * GN + c] = make_float2(acc[mt][nt][2], acc[mt][nt][3]);
            }
        }
    }
}

// Fused QKV: blockIdx.z selects weight + destination
__global__ __launch_bounds__(256, 1) void gemm_qkv(const __half* __restrict__ A,
                                                   const __half* __restrict__ Wbase,
                                                   __half* __restrict__ Cq,
                                                   __half* __restrict__ Ck,
                                                   __half* __restrict__ Cv_)
{
    extern __shared__ uint32_t smw[];
    const int z = blockIdx.z;
    const __half* W = Wbase + (size_t)z * Dd * Dd;
    __half* C = (z == 0) ? Cq : ((z == 1) ? Ck : Cv_);
    gemm_core(A, W, (void*)C, 1, smem_u32(smw));
}

__global__ __launch_bounds__(256, 1) void gemm_o(const __half* __restrict__ A,
                                                 const __half* __restrict__ W,
                                                 float* __restrict__ C)
{
    extern __shared__ uint32_t smw[];
    gemm_core(A, W, (void*)C, 0, smem_u32(smw));
}

// ------------------------------------------------------------------
// RoPE in place on half data (grid.y selects Q or K)
// ------------------------------------------------------------------
__global__ void rope_h2(__half* __restrict__ Pq, __half* __restrict__ Pk,
                        const float* __restrict__ cosT,
                        const float* __restrict__ sinT)
{
    __half* P = blockIdx.y ? Pk : Pq;
    int idx = blockIdx.x * blockDim.x + threadIdx.x;
    int hd  = idx & 63;
    int h   = (idx >> 6) & (Hh - 1);
    int row = idx >> 10;
    int s   = row & (Ss - 1);
    size_t base = (size_t)row * Dd + h * HDd;
    float q1 = __half2float(P[base + hd]);
    float q2 = __half2float(P[base + hd + 64]);
    float c1 = cosT[s*HDd + hd],      s1 = sinT[s*HDd + hd];
    float c2 = cosT[s*HDd + hd + 64], s2 = sinT[s*HDd + hd + 64];
    P[base + hd]      = __float2half_rn(q1 * c1 - q2 * s1);
    P[base + hd + 64] = __float2half_rn(q2 * c2 + q1 * s2);
}

// ------------------------------------------------------------------
// Flash attention (unchanged from R13): fp16, ldmatrix, 128-q tiles,
// 64-row KV tiles, 8 warps, 2 CTAs/SM, heavy tiles first.
// ------------------------------------------------------------------
#define QTA 128
#define KTA 64
#define ASTR 68
#define QWRD (QTA*ASTR)
#define KWRD (KTA*ASTR)
#define ATTN_SMEM ((QWRD + 4*KWRD)*4)   // 104448 B

__global__ __launch_bounds__(256, 2) void attn_h()
{
    extern __shared__ uint32_t sw[];
    const int tid  = threadIdx.x;
    const int lane = tid & 31, warp = tid >> 5;
    const int t = lane & 3;
    const int qtile = (gridDim.x - 1) - blockIdx.x;
    const int bh = blockIdx.y;
    const int b  = bh >> 4, h = bh & 15;
    const int q0 = qtile * QTA;

    const uint32_t sbase = smem_u32(sw);
    const uint32_t qa  = sbase;
    const uint32_t k0a = sbase + QWRD*4;
    const uint32_t k1a = k0a + KWRD*4;
    const uint32_t v0a = k1a + KWRD*4;
    const uint32_t v1a = v0a + KWRD*4;

    const size_t kvcol = (size_t)h * HDd;

    {   // prologue: Q tile + KV tile 0
        #pragma unroll
        for (int i = 0; i < 8; i++) {
            int idx = tid + i * 256;
            int r = idx >> 4, c = idx & 15;
            uint32_t dof = (uint32_t)(r*ASTR + c*4) * 4u;
            size_t gq = (size_t)(b*Ss + q0 + r) * Dd + kvcol + c*8;
            CP_ASYNC16(qa + dof, g_Qh + gq);
        }
        #pragma unroll
        for (int i = 0; i < 4; i++) {
            int idx = tid + i * 256;
            int r = idx >> 4, c = idx & 15;
            uint32_t dof = (uint32_t)(r*ASTR + c*4) * 4u;
            size_t gk = (size_t)(b*Ss + r) * Dd + kvcol + c*8;
            CP_ASYNC16(k0a + dof, g_Kh + gk);
            CP_ASYNC16(v0a + dof, g_Vh + gk);
        }
        CP_COMMIT();
    }

    const uint32_t q_off = (uint32_t)((warp*16 + (lane & 15)) * ASTR
                                      + ((lane >> 4) << 2)) * 4u;
    const uint32_t k_off = (uint32_t)(((lane & 7) + ((lane >> 4) << 3)) * ASTR
                                      + (((lane >> 3) & 1) << 2)) * 4u;
    const uint32_t v_off = (uint32_t)((lane & 15) * ASTR) * 4u
                         + ((uint32_t)(lane >> 4) << 4);

    float accO[16][4];
    #pragma unroll
    for (int nt = 0; nt < 16; nt++)
        #pragma unroll
        for (int e = 0; e < 4; e++) accO[nt][e] = 0.f;
    float m0 = -INFINITY, m1 = -INFINITY, l0 = 0.f, l1 = 0.f;

    const int g = lane >> 2;
    const int row0 = q0 + warp*16 + g;
    const int row1 = row0 + 8;
    const int nj = 2*qtile + 2;

    for (int jt = 0; jt < nj; jt++) {
        CP_WAIT(0);
        __syncthreads();

        if (jt + 1 < nj) {
            const uint32_t ka = ((jt + 1) & 1) ? k1a : k0a;
            const uint32_t va = ((jt + 1) & 1) ? v1a : v0a;
            const int jrow = (jt + 1) * KTA;
            #pragma unroll
            for (int i = 0; i < 4; i++) {
                int idx = tid + i * 256;
                int r = idx >> 4, c = idx & 15;
                uint32_t dof = (uint32_t)(r*ASTR + c*4) * 4u;
                size_t gk = (size_t)(b*Ss + jrow + r) * Dd + kvcol + c*8;
                CP_ASYNC16(ka + dof, g_Kh + gk);
                CP_ASYNC16(va + dof, g_Vh + gk);
            }
            CP_COMMIT();
        }

        const uint32_t ka = (jt & 1) ? k1a : k0a;
        const uint32_t va = (jt & 1) ? v1a : v0a;
        const int j = jt * KTA;

        float sc[8][4];
        #pragma unroll
        for (int nt = 0; nt < 8; nt++)
            #pragma unroll
            for (int e = 0; e < 4; e++) sc[nt][e] = 0.f;

        #pragma unroll
        for (int ch = 0; ch < 8; ch++) {
            const uint32_t kso = (uint32_t)(ch * 8) * 4u;
            uint32_t a[4], bf[8][2];
            ldm_x4(a[0], a[1], a[2], a[3], qa + q_off + kso);
            #pragma unroll
            for (int p = 0; p < 4; p++)
                ldm_x4(bf[2*p][0], bf[2*p][1], bf[2*p+1][0], bf[2*p+1][1],
                       ka + k_off + kso + (uint32_t)(p*16*ASTR)*4u);
            #pragma unroll
            for (int nt = 0; nt < 8; nt++)
                mma_f16(sc[nt], a, bf[nt][0], bf[nt][1]);
        }

        const bool diag = (j >= q0);
        #pragma unroll
        for (int nt = 0; nt < 8; nt++) {
            int col = j + nt*8 + t*2;
            sc[nt][0] *= ATTN_SCALE; sc[nt][1] *= ATTN_SCALE;
            sc[nt][2] *= ATTN_SCALE; sc[nt][3] *= ATTN_SCALE;
            if (diag) {
                if (col     > row0) sc[nt][0] = -INFINITY;
                if (col + 1 > row0) sc[nt][1] = -INFINITY;
                if (col     > row1) sc[nt][2] = -INFINITY;
                if (col + 1 > row1) sc[nt][3] = -INFINITY;
            }
        }

        float rm0 = -INFINITY, rm1 = -INFINITY;
        #pragma unroll
        for (int nt = 0; nt < 8; nt++) {
            rm0 = fmaxf(rm0, fmaxf(sc[nt][0], sc[nt][1]));
            rm1 = fmaxf(rm1, fmaxf(sc[nt][2], sc[nt][3]));
        }
        rm0 = fmaxf(rm0, __shfl_xor_sync(0xffffffffu, rm0, 1));
        rm0 = fmaxf(rm0, __shfl_xor_sync(0xffffffffu, rm0, 2));
        rm1 = fmaxf(rm1, __shfl_xor_sync(0xffffffffu, rm1, 1));
        rm1 = fmaxf(rm1, __shfl_xor_sync(0xffffffffu, rm1, 2));

        float m0n = fmaxf(m0, rm0), m1n = fmaxf(m1, rm1);
        float al0 = __expf(m0 - m0n), al1 = __expf(m1 - m1n);
        float sum0 = 0.f, sum1 = 0.f;
        uint32_t ph[8][2];
        #pragma unroll
        for (int nt = 0; nt < 8; nt++) {
            float p0 = __expf(sc[nt][0] - m0n);
            float p1 = __expf(sc[nt][1] - m0n);
            float p2 = __expf(sc[nt][2] - m1n);
            float p3 = __expf(sc[nt][3] - m1n);
            sum0 += p0 + p1; sum1 += p2 + p3;
            ph[nt][0] = pk2(p0, p1);
            ph[nt][1] = pk2(p2, p3);
        }
        sum0 += __shfl_xor_sync(0xffffffffu, sum0, 1);
        sum0 += __shfl_xor_sync(0xffffffffu, sum0, 2);
        sum1 += __shfl_xor_sync(0xffffffffu, sum1, 1);
        sum1 += __shfl_xor_sync(0xffffffffu, sum1, 2);
        l0 = l0 * al0 + sum0;
        l1 = l1 * al1 + sum1;
        m0 = m0n; m1 = m1n;
        #pragma unroll
        for (int nt = 0; nt < 16; nt++) {
            accO[nt][0] *= al0; accO[nt][1] *= al0;
            accO[nt][2] *= al1; accO[nt][3] *= al1;
        }

        #pragma unroll
        for (int kc = 0; kc < 4; kc++) {
            const int n0 = kc * 2;
            uint32_t a[4];
            a[0] = ph[n0][0];     a[1] = ph[n0][1];
            a[2] = ph[n0+1][0];   a[3] = ph[n0+1][1];
            const uint32_t vb = va + (uint32_t)(kc*16*ASTR)*4u + v_off;
            #pragma unroll
            for (int np = 0; np < 8; np++) {
                uint32_t b0, b1, b2, b3;
                ldm_x4_t(b0, b1, b2, b3, vb + np*32);
                mma_f16(accO[2*np],   a, b0, b1);
                mma_f16(accO[2*np+1], a, b2, b3);
            }
        }
    }

    float inv0 = 1.f / l0, inv1 = 1.f / l1;
    uint32_t* Aw = (uint32_t*)g_Ah;
    size_t ob0 = ((size_t)(b*Ss + q0 + warp*16 + g) * Dd + h * HDd) >> 1;
    size_t ob1 = ob0 + 4*Dd;
    #pragma unroll
    for (int nt = 0; nt < 16; nt++) {
        int cw = nt*4 + t;
        Aw[ob0 + cw] = pk2(accO[nt][0] * inv0, accO[nt][1] * inv0);
        Aw[ob1 + cw] = pk2(accO[nt][2] * inv1, accO[nt][3] * inv1);
    }
}

// ============================================================
extern "C" void kernel_launch(void* const* d_in, const int* in_sizes, int n_in,
                              void* d_out, int out_size)
{
    (void)in_sizes; (void)n_in; (void)out_size;
    const float* x    = (const float*)d_in[0];
    // d_in[1] = mask (unused -- causal implemented directly)
    const float* cosT = (const float*)d_in[2];
    const float* sinT = (const float*)d_in[3];
    const float* Wq   = (const float*)d_in[4];
    const float* Wk   = (const float*)d_in[5];
    const float* Wv   = (const float*)d_in[6];
    const float* Wo   = (const float*)d_in[7];
    float* out = (float*)d_out;

    __half *xh, *wh, *qh, *kh, *vh, *ah;
    cudaGetSymbolAddress((void**)&xh, g_Xh);
    cudaGetSymbolAddress((void**)&wh, g_Wh);
    cudaGetSymbolAddress((void**)&qh, g_Qh);
    cudaGetSymbolAddress((void**)&kh, g_Kh);
    cudaGetSymbolAddress((void**)&vh, g_Vh);
    cudaGetSymbolAddress((void**)&ah, g_Ah);
    __half* wqh = wh;
    __half* wkh = wh + (size_t)Dd*Dd;
    __half* wvh = wh + 2*(size_t)Dd*Dd;
    __half* woh = wh + 3*(size_t)Dd*Dd;

    pack_half<<<(MROWS*Dd/4)/256, 256>>>((const float4*)x, (uint32_t*)xh, MROWS*Dd/4);
    pack_half2<<<dim3((Dd*Dd/4)/256, 2), 256>>>((const float4*)Wq, (uint32_t*)wqh,
                                                (const float4*)Wk, (uint32_t*)wkh, Dd*Dd/4);
    pack_half2<<<dim3((Dd*Dd/4)/256, 2), 256>>>((const float4*)Wv, (uint32_t*)wvh,
                                                (const float4*)Wo, (uint32_t*)woh, Dd*Dd/4);

    cudaFuncSetAttribute(gemm_qkv, cudaFuncAttributeMaxDynamicSharedMemorySize, G_SMEM);
    cudaFuncSetAttribute(gemm_o,   cudaFuncAttributeMaxDynamicSharedMemorySize, G_SMEM);

    // launch 3: fused QKV (256 CTAs per projection, z = 0/1/2)
    gemm_qkv<<<dim3(GN/256, GM/128, 3), 256, G_SMEM>>>(xh, wh, qh, kh, vh);

    int nrope = MROWS * Hh * 64;
    rope_h2<<<dim3(nrope / 256, 2), 256>>>(qh, kh, cosT, sinT);    // launch 4

    cudaFuncSetAttribute(attn_h, cudaFuncAttributeMaxDynamicSharedMemorySize, ATTN_SMEM);
    attn_h<<<dim3(Ss / QTA, Bb * Hh), 256, ATTN_SMEM>>>();         // launch 5 <- ncu

    gemm_o<<<dim3(GN/256, GM/128), 256, G_SMEM>>>(ah, woh, out);
}

// round 15
// speedup vs baseline: 1.1932x; 1.1932x over previous
#include <cuda_runtime.h>
#include <cuda_fp16.h>
#include <cstdint>

// Problem constants
#define Bb 2
#define Ss 2048
#define Dd 2048
#define Hh 16
#define HDd 128
#define MROWS (Bb*Ss)              // 4096
#define ATTN_SCALE 0.08838834764831845f  // 1/sqrt(128)

// Scratch (static device globals: allocation-free rule)
__device__ __half g_Xh[(size_t)MROWS*Dd];
__device__ __half g_Wh[4][(size_t)Dd*Dd];
__device__ __half g_Qh[(size_t)MROWS*Dd];
__device__ __half g_Kh[(size_t)MROWS*Dd];
__device__ __half g_Vh[(size_t)MROWS*Dd];
__device__ __half g_Ah[(size_t)MROWS*Dd];

// ------------------------------------------------------------------
// helpers
// ------------------------------------------------------------------
__device__ __forceinline__ uint32_t pk2(float a, float b){
    __half2 h = __floats2half2_rn(a, b);
    return *reinterpret_cast<uint32_t*>(&h);
}
__device__ __forceinline__ uint32_t smem_u32(const void* p){
    uint32_t a;
    asm("{ .reg .u64 t; cvta.to.shared.u64 t, %1; cvt.u32.u64 %0, t; }"
        : "=r"(a) : "l"(p));
    return a;
}
__device__ __forceinline__ void mma_f16(float c[4], const uint32_t a[4],
                                        uint32_t b0, uint32_t b1){
    asm volatile("mma.sync.aligned.m16n8k16.row.col.f32.f16.f16.f32 "
        "{%0,%1,%2,%3}, {%4,%5,%6,%7}, {%8,%9}, {%0,%1,%2,%3};\n"
        : "+f"(c[0]), "+f"(c[1]), "+f"(c[2]), "+f"(c[3])
        : "r"(a[0]), "r"(a[1]), "r"(a[2]), "r"(a[3]), "r"(b0), "r"(b1));
}
__device__ __forceinline__ void ldm_x4(uint32_t &r0, uint32_t &r1,
                                       uint32_t &r2, uint32_t &r3, uint32_t addr){
    asm volatile("ldmatrix.sync.aligned.m8n8.x4.shared.b16 {%0,%1,%2,%3}, [%4];"
        : "=r"(r0), "=r"(r1), "=r"(r2), "=r"(r3) : "r"(addr));
}
__device__ __forceinline__ void ldm_x4_t(uint32_t &r0, uint32_t &r1,
                                         uint32_t &r2, uint32_t &r3, uint32_t addr){
    asm volatile("ldmatrix.sync.aligned.m8n8.x4.trans.shared.b16 {%0,%1,%2,%3}, [%4];"
        : "=r"(r0), "=r"(r1), "=r"(r2), "=r"(r3) : "r"(addr));
}

#define CP_ASYNC16(sa, ga) \
    asm volatile("cp.async.cg.shared.global [%0], [%1], 16;" :: "r"(sa), "l"(ga))
#define CP_COMMIT() asm volatile("cp.async.commit_group;" ::: "memory")
#define CP_WAIT(n)  asm volatile("cp.async.wait_group %0;" :: "n"(n) : "memory")

// ------------------------------------------------------------------
// pack fp32 -> fp16
// ------------------------------------------------------------------
__global__ void pack_half(const float4* __restrict__ in, uint32_t* __restrict__ out,
                          int n4){
    int i = blockIdx.x * blockDim.x + threadIdx.x;
    if (i < n4) {
        float4 v = in[i];
        out[2*i]   = pk2(v.x, v.y);
        out[2*i+1] = pk2(v.z, v.w);
    }
}
__global__ void pack_half2(const float4* __restrict__ in0, uint32_t* __restrict__ out0,
                           const float4* __restrict__ in1, uint32_t* __restrict__ out1,
                           int n4){
    int i = blockIdx.x * blockDim.x + threadIdx.x;
    if (i >= n4) return;
    const float4* in = blockIdx.y ? in1 : in0;
    uint32_t* out = blockIdx.y ? out1 : out0;
    float4 v = in[i];
    out[2*i]   = pk2(v.x, v.y);
    out[2*i+1] = pk2(v.z, v.w);
}

// ------------------------------------------------------------------
// GEMM core (R13-proven config): C[M,N] = A[M,K] * W[N,K]^T
// 128x128 CTA, 8 warps (4x2) of 32x64, BK=32 halves, 4-stage cp.async,
// 2 CTAs/SM (80KB smem, 128 regs). Fragments via ldmatrix.x4.
// ------------------------------------------------------------------
#define GM 4096
#define GN 2048
#define GK 2048
#define BKH 32
#define SSTR 20
#define A_WORDS (128*SSTR)
#define B_WORDS (128*SSTR)
#define STG_WORDS (A_WORDS + B_WORDS)
#define G_STAGES 4
#define G_SMEM (G_STAGES*STG_WORDS*4)   // 81920 B
#define G_NK (GK/BKH)

__device__ __forceinline__ void gemm_core(const __half* __restrict__ A,
                                          const __half* __restrict__ W,
                                          void* __restrict__ Cv, int outh,
                                          uint32_t smem_base)
{
    const int tid  = threadIdx.x;
    const int lane = tid & 31, warp = tid >> 5;
    const int wm = warp >> 1, wn = warp & 1;      // 4 x 2 warp grid (32x64 tiles)
    const int g = lane >> 2, t = lane & 3;
    const int bM = blockIdx.y * 128, bN = blockIdx.x * 128;

    const int frow = tid >> 2, fc = tid & 3;
    const __half* Ag = A + (size_t)(bM + frow) * GK + fc * 8;
    const __half* Wg = W + (size_t)(bN + frow) * GK + fc * 8;
    const uint32_t fillA = smem_base + (uint32_t)(frow * SSTR + fc * 4) * 4u;
    const uint32_t fillB = smem_base + (uint32_t)(A_WORDS + frow * SSTR + fc * 4) * 4u;

    const int a_row = wm*32 + (lane & 15);
    const int a_col = (lane >> 4) << 2;
    const int b_row = wn*64 + (lane & 7) + ((lane >> 4) << 3);
    const int b_col = ((lane >> 3) & 1) << 2;
    const uint32_t aoff = (uint32_t)(a_row * SSTR + a_col) * 4u;
    const uint32_t boff = (uint32_t)(A_WORDS + b_row * SSTR + b_col) * 4u;

    float acc[2][8][4];
    #pragma unroll
    for (int mt = 0; mt < 2; mt++)
        #pragma unroll
        for (int nt = 0; nt < 8; nt++)
            #pragma unroll
            for (int e = 0; e < 4; e++) acc[mt][nt][e] = 0.f;

    #pragma unroll
    for (int s = 0; s < G_STAGES - 1; s++) {
        uint32_t sa = fillA + s * (STG_WORDS * 4);
        uint32_t sw = fillB + s * (STG_WORDS * 4);
        const __half* ap = Ag + s * BKH;
        const __half* wp = Wg + s * BKH;
        CP_ASYNC16(sa, ap);
        CP_ASYNC16(sa + 64*SSTR*4, ap + (size_t)64 * GK);
        CP_ASYNC16(sw, wp);
        CP_ASYNC16(sw + 64*SSTR*4, wp + (size_t)64 * GK);
        CP_COMMIT();
    }

    for (int kt = 0; kt < G_NK; kt++) {
        CP_WAIT(2);
        __syncthreads();

        {
            const int pf = kt + G_STAGES - 1;
            if (pf < G_NK) {
                const int sp = pf & (G_STAGES - 1);
                uint32_t sa = fillA + sp * (STG_WORDS * 4);
                uint32_t sw = fillB + sp * (STG_WORDS * 4);
                const __half* ap = Ag + pf * BKH;
                const __half* wp = Wg + pf * BKH;
                CP_ASYNC16(sa, ap);
                CP_ASYNC16(sa + 64*SSTR*4, ap + (size_t)64 * GK);
                CP_ASYNC16(sw, wp);
                CP_ASYNC16(sw + 64*SSTR*4, wp + (size_t)64 * GK);
            }
            CP_COMMIT();
        }

        const uint32_t sbase = smem_base + (kt & (G_STAGES - 1)) * (STG_WORDS * 4);
        #pragma unroll
        for (int ks = 0; ks < 2; ks++) {
            const uint32_t kso = (uint32_t)(ks * 8) * 4u;
            uint32_t af[2][4], bf[8][2];
            #pragma unroll
            for (int mt = 0; mt < 2; mt++)
                ldm_x4(af[mt][0], af[mt][1], af[mt][2], af[mt][3],
                       sbase + aoff + kso + (uint32_t)(mt*16*SSTR)*4u);
            #pragma unroll
            for (int p = 0; p < 4; p++)
                ldm_x4(bf[2*p][0], bf[2*p][1], bf[2*p+1][0], bf[2*p+1][1],
                       sbase + boff + kso + (uint32_t)(p*16*SSTR)*4u);
            #pragma unroll
            for (int mt = 0; mt < 2; mt++)
                #pragma unroll
                for (int nt = 0; nt < 8; nt++)
                    mma_f16(acc[mt][nt], af[mt], bf[nt][0], bf[nt][1]);
        }
        __syncthreads();
    }

    if (outh) {
        uint32_t* Cw = (uint32_t*)Cv;
        #pragma unroll
        for (int mt = 0; mt < 2; mt++) {
            int r = bM + wm*32 + mt*16 + g;
            #pragma unroll
            for (int nt = 0; nt < 8; nt++) {
                int c = bN + wn*64 + nt*8 + t*2;
                Cw[(size_t)r * (GN/2)       + (c >> 1)] = pk2(acc[mt][nt][0], acc[mt][nt][1]);
                Cw[(size_t)(r + 8) * (GN/2) + (c >> 1)] = pk2(acc[mt][nt][2], acc[mt][nt][3]);
            }
        }
    } else {
        float* C = (float*)Cv;
        #pragma unroll
        for (int mt = 0; mt < 2; mt++) {
            int r = bM + wm*32 + mt*16 + g;
            #pragma unroll
            for (int nt = 0; nt < 8; nt++) {
                int c = bN + wn*64 + nt*8 + t*2;
                *(float2*)&C[(size_t)r * GN + c]       = make_float2(acc[mt][nt][0], acc[mt][nt][1]);
                *(float2*)&C[(size_t)(r + 8) * GN + c] = make_float2(acc[mt][nt][2], acc[mt][nt][3]);
            }
        }
    }
}

// Fused QKV: blockIdx.z selects weight + destination
__global__ __launch_bounds__(256, 2) void gemm_qkv(const __half* __restrict__ A,
                                                   const __half* __restrict__ Wbase,
                                                   __half* __restrict__ Cq,
                                                   __half* __restrict__ Ck,
                                                   __half* __restrict__ Cv_)
{
    extern __shared__ uint32_t smw[];
    const int z = blockIdx.z;
    const __half* W = Wbase + (size_t)z * Dd * Dd;
    __half* C = (z == 0) ? Cq : ((z == 1) ? Ck : Cv_);
    gemm_core(A, W, (void*)C, 1, smem_u32(smw));
}

__global__ __launch_bounds__(256, 2) void gemm_o(const __half* __restrict__ A,
                                                 const __half* __restrict__ W,
                                                 float* __restrict__ C)
{
    extern __shared__ uint32_t smw[];
    gemm_core(A, W, (void*)C, 0, smem_u32(smw));
}

// ------------------------------------------------------------------
// RoPE in place on half data (grid.y selects Q or K)
// ------------------------------------------------------------------
__global__ void rope_h2(__half* __restrict__ Pq, __half* __restrict__ Pk,
                        const float* __restrict__ cosT,
                        const float* __restrict__ sinT)
{
    __half* P = blockIdx.y ? Pk : Pq;
    int idx = blockIdx.x * blockDim.x + threadIdx.x;
    int hd  = idx & 63;
    int h   = (idx >> 6) & (Hh - 1);
    int row = idx >> 10;
    int s   = row & (Ss - 1);
    size_t base = (size_t)row * Dd + h * HDd;
    float q1 = __half2float(P[base + hd]);
    float q2 = __half2float(P[base + hd + 64]);
    float c1 = cosT[s*HDd + hd],      s1 = sinT[s*HDd + hd];
    float c2 = cosT[s*HDd + hd + 64], s2 = sinT[s*HDd + hd + 64];
    P[base + hd]      = __float2half_rn(q1 * c1 - q2 * s1);
    P[base + hd + 64] = __float2half_rn(q2 * c2 + q1 * s2);
}

// ------------------------------------------------------------------
// Flash attention (R13-proven): fp16, ldmatrix, 128-q tiles,
// 64-row KV tiles, 8 warps, 2 CTAs/SM, heavy tiles first.
// ------------------------------------------------------------------
#define QTA 128
#define KTA 64
#define ASTR 68
#define QWRD (QTA*ASTR)
#define KWRD (KTA*ASTR)
#define ATTN_SMEM ((QWRD + 4*KWRD)*4)   // 104448 B

__global__ __launch_bounds__(256, 2) void attn_h()
{
    extern __shared__ uint32_t sw[];
    const int tid  = threadIdx.x;
    const int lane = tid & 31, warp = tid >> 5;
    const int t = lane & 3;
    const int qtile = (gridDim.x - 1) - blockIdx.x;
    const int bh = blockIdx.y;
    const int b  = bh >> 4, h = bh & 15;
    const int q0 = qtile * QTA;

    const uint32_t sbase = smem_u32(sw);
    const uint32_t qa  = sbase;
    const uint32_t k0a = sbase + QWRD*4;
    const uint32_t k1a = k0a + KWRD*4;
    const uint32_t v0a = k1a + KWRD*4;
    const uint32_t v1a = v0a + KWRD*4;

    const size_t kvcol = (size_t)h * HDd;

    {   // prologue: Q tile + KV tile 0
        #pragma unroll
        for (int i = 0; i < 8; i++) {
            int idx = tid + i * 256;
            int r = idx >> 4, c = idx & 15;
            uint32_t dof = (uint32_t)(r*ASTR + c*4) * 4u;
            size_t gq = (size_t)(b*Ss + q0 + r) * Dd + kvcol + c*8;
            CP_ASYNC16(qa + dof, g_Qh + gq);
        }
        #pragma unroll
        for (int i = 0; i < 4; i++) {
            int idx = tid + i * 256;
            int r = idx >> 4, c = idx & 15;
            uint32_t dof = (uint32_t)(r*ASTR + c*4) * 4u;
            size_t gk = (size_t)(b*Ss + r) * Dd + kvcol + c*8;
            CP_ASYNC16(k0a + dof, g_Kh + gk);
            CP_ASYNC16(v0a + dof, g_Vh + gk);
        }
        CP_COMMIT();
    }

    const uint32_t q_off = (uint32_t)((warp*16 + (lane & 15)) * ASTR
                                      + ((lane >> 4) << 2)) * 4u;
    const uint32_t k_off = (uint32_t)(((lane & 7) + ((lane >> 4) << 3)) * ASTR
                                      + (((lane >> 3) & 1) << 2)) * 4u;
    const uint32_t v_off = (uint32_t)((lane & 15) * ASTR) * 4u
                         + ((uint32_t)(lane >> 4) << 4);

    float accO[16][4];
    #pragma unroll
    for (int nt = 0; nt < 16; nt++)
        #pragma unroll
        for (int e = 0; e < 4; e++) accO[nt][e] = 0.f;
    float m0 = -INFINITY, m1 = -INFINITY, l0 = 0.f, l1 = 0.f;

    const int g = lane >> 2;
    const int row0 = q0 + warp*16 + g;
    const int row1 = row0 + 8;
    const int nj = 2*qtile + 2;

    for (int jt = 0; jt < nj; jt++) {
        CP_WAIT(0);
        __syncthreads();

        if (jt + 1 < nj) {
            const uint32_t ka = ((jt + 1) & 1) ? k1a : k0a;
            const uint32_t va = ((jt + 1) & 1) ? v1a : v0a;
            const int jrow = (jt + 1) * KTA;
            #pragma unroll
            for (int i = 0; i < 4; i++) {
                int idx = tid + i * 256;
                int r = idx >> 4, c = idx & 15;
                uint32_t dof = (uint32_t)(r*ASTR + c*4) * 4u;
                size_t gk = (size_t)(b*Ss + jrow + r) * Dd + kvcol + c*8;
                CP_ASYNC16(ka + dof, g_Kh + gk);
                CP_ASYNC16(va + dof, g_Vh + gk);
            }
            CP_COMMIT();
        }

        const uint32_t ka = (jt & 1) ? k1a : k0a;
        const uint32_t va = (jt & 1) ? v1a : v0a;
        const int j = jt * KTA;

        float sc[8][4];
        #pragma unroll
        for (int nt = 0; nt < 8; nt++)
            #pragma unroll
            for (int e = 0; e < 4; e++) sc[nt][e] = 0.f;

        #pragma unroll
        for (int ch = 0; ch < 8; ch++) {
            const uint32_t kso = (uint32_t)(ch * 8) * 4u;
            uint32_t a[4], bf[8][2];
            ldm_x4(a[0], a[1], a[2], a[3], qa + q_off + kso);
            #pragma unroll
            for (int p = 0; p < 4; p++)
                ldm_x4(bf[2*p][0], bf[2*p][1], bf[2*p+1][0], bf[2*p+1][1],
                       ka + k_off + kso + (uint32_t)(p*16*ASTR)*4u);
            #pragma unroll
            for (int nt = 0; nt < 8; nt++)
                mma_f16(sc[nt], a, bf[nt][0], bf[nt][1]);
        }

        const bool diag = (j >= q0);
        #pragma unroll
        for (int nt = 0; nt < 8; nt++) {
            int col = j + nt*8 + t*2;
            sc[nt][0] *= ATTN_SCALE; sc[nt][1] *= ATTN_SCALE;
            sc[nt][2] *= ATTN_SCALE; sc[nt][3] *= ATTN_SCALE;
            if (diag) {
                if (col     > row0) sc[nt][0] = -INFINITY;
                if (col + 1 > row0) sc[nt][1] = -INFINITY;
                if (col     > row1) sc[nt][2] = -INFINITY;
                if (col + 1 > row1) sc[nt][3] = -INFINITY;
            }
        }

        float rm0 = -INFINITY, rm1 = -INFINITY;
        #pragma unroll
        for (int nt = 0; nt < 8; nt++) {
            rm0 = fmaxf(rm0, fmaxf(sc[nt][0], sc[nt][1]));
            rm1 = fmaxf(rm1, fmaxf(sc[nt][2], sc[nt][3]));
        }
        rm0 = fmaxf(rm0, __shfl_xor_sync(0xffffffffu, rm0, 1));
        rm0 = fmaxf(rm0, __shfl_xor_sync(0xffffffffu, rm0, 2));
        rm1 = fmaxf(rm1, __shfl_xor_sync(0xffffffffu, rm1, 1));
        rm1 = fmaxf(rm1, __shfl_xor_sync(0xffffffffu, rm1, 2));

        float m0n = fmaxf(m0, rm0), m1n = fmaxf(m1, rm1);
        float al0 = __expf(m0 - m0n), al1 = __expf(m1 - m1n);
        float sum0 = 0.f, sum1 = 0.f;
        uint32_t ph[8][2];
        #pragma unroll
        for (int nt = 0; nt < 8; nt++) {
            float p0 = __expf(sc[nt][0] - m0n);
            float p1 = __expf(sc[nt][1] - m0n);
            float p2 = __expf(sc[nt][2] - m1n);
            float p3 = __expf(sc[nt][3] - m1n);
            sum0 += p0 + p1; sum1 += p2 + p3;
            ph[nt][0] = pk2(p0, p1);
            ph[nt][1] = pk2(p2, p3);
        }
        sum0 += __shfl_xor_sync(0xffffffffu, sum0, 1);
        sum0 += __shfl_xor_sync(0xffffffffu, sum0, 2);
        sum1 += __shfl_xor_sync(0xffffffffu, sum1, 1);
        sum1 += __shfl_xor_sync(0xffffffffu, sum1, 2);
        l0 = l0 * al0 + sum0;
        l1 = l1 * al1 + sum1;
        m0 = m0n; m1 = m1n;
        #pragma unroll
        for (int nt = 0; nt < 16; nt++) {
            accO[nt][0] *= al0; accO[nt][1] *= al0;
            accO[nt][2] *= al1; accO[nt][3] *= al1;
        }

        #pragma unroll
        for (int kc = 0; kc < 4; kc++) {
            const int n0 = kc * 2;
            uint32_t a[4];
            a[0] = ph[n0][0];     a[1] = ph[n0][1];
            a[2] = ph[n0+1][0];   a[3] = ph[n0+1][1];
            const uint32_t vb = va + (uint32_t)(kc*16*ASTR)*4u + v_off;
            #pragma unroll
            for (int np = 0; np < 8; np++) {
                uint32_t b0, b1, b2, b3;
                ldm_x4_t(b0, b1, b2, b3, vb + np*32);
                mma_f16(accO[2*np],   a, b0, b1);
                mma_f16(accO[2*np+1], a, b2, b3);
            }
        }
    }

    float inv0 = 1.f / l0, inv1 = 1.f / l1;
    uint32_t* Aw = (uint32_t*)g_Ah;
    size_t ob0 = ((size_t)(b*Ss + q0 + warp*16 + g) * Dd + h * HDd) >> 1;
    size_t ob1 = ob0 + 4*Dd;
    #pragma unroll
    for (int nt = 0; nt < 16; nt++) {
        int cw = nt*4 + t;
        Aw[ob0 + cw] = pk2(accO[nt][0] * inv0, accO[nt][1] * inv0);
        Aw[ob1 + cw] = pk2(accO[nt][2] * inv1, accO[nt][3] * inv1);
    }
}

// ============================================================
extern "C" void kernel_launch(void* const* d_in, const int* in_sizes, int n_in,
                              void* d_out, int out_size)
{
    (void)in_sizes; (void)n_in; (void)out_size;
    const float* x    = (const float*)d_in[0];
    // d_in[1] = mask (unused -- causal implemented directly)
    const float* cosT = (const float*)d_in[2];
    const float* sinT = (const float*)d_in[3];
    const float* Wq   = (const float*)d_in[4];
    const float* Wk   = (const float*)d_in[5];
    const float* Wv   = (const float*)d_in[6];
    const float* Wo   = (const float*)d_in[7];
    float* out = (float*)d_out;

    __half *xh, *wh, *qh, *kh, *vh, *ah;
    cudaGetSymbolAddress((void**)&xh, g_Xh);
    cudaGetSymbolAddress((void**)&wh, g_Wh);
    cudaGetSymbolAddress((void**)&qh, g_Qh);
    cudaGetSymbolAddress((void**)&kh, g_Kh);
    cudaGetSymbolAddress((void**)&vh, g_Vh);
    cudaGetSymbolAddress((void**)&ah, g_Ah);
    __half* wqh = wh;
    __half* wkh = wh + (size_t)Dd*Dd;
    __half* wvh = wh + 2*(size_t)Dd*Dd;
    __half* woh = wh + 3*(size_t)Dd*Dd;

    pack_half<<<(MROWS*Dd/4)/256, 256>>>((const float4*)x, (uint32_t*)xh, MROWS*Dd/4);
    pack_half2<<<dim3((Dd*Dd/4)/256, 2), 256>>>((const float4*)Wq, (uint32_t*)wqh,
                                                (const float4*)Wk, (uint32_t*)wkh, Dd*Dd/4);
    pack_half2<<<dim3((Dd*Dd/4)/256, 2), 256>>>((const float4*)Wv, (uint32_t*)wvh,
                                                (const float4*)Wo, (uint32_t*)woh, Dd*Dd/4);

    cudaFuncSetAttribute(gemm_qkv, cudaFuncAttributeMaxDynamicSharedMemorySize, G_SMEM);
    cudaFuncSetAttribute(gemm_o,   cudaFuncAttributeMaxDynamicSharedMemorySize, G_SMEM);

    // launch 3: fused QKV (512 CTAs per projection, z = 0/1/2)
    gemm_qkv<<<dim3(GN/128, GM/128, 3), 256, G_SMEM>>>(xh, wh, qh, kh, vh);

    int nrope = MROWS * Hh * 64;
    rope_h2<<<dim3(nrope / 256, 2), 256>>>(qh, kh, cosT, sinT);    // launch 4

    cudaFuncSetAttribute(attn_h, cudaFuncAttributeMaxDynamicSharedMemorySize, ATTN_SMEM);
    attn_h<<<dim3(Ss / QTA, Bb * Hh), 256, ATTN_SMEM>>>();         // launch 5 <- ncu

    gemm_o<<<dim3(GN/128, GM/128), 256, G_SMEM>>>(ah, woh, out);
}